// round 1
// baseline (speedup 1.0000x reference)
#include <cuda_runtime.h>

#define NN 50000
#define EE 600000
#define FF 128
#define RR 4

// ---------------- scratch (static device globals; no allocation) ----------------
__device__ __align__(16) float g_agg[(size_t)RR * NN * FF];   // x + sum of neighbors, per relation
__device__ __align__(16) float g_h[(size_t)RR * NN * FF];     // output of first linear layer
__device__ float g_sum[RR * FF];
__device__ float g_sumsq[RR * FF];
__device__ float g_scale[RR * FF];
__device__ float g_shift[RR * FF];

typedef unsigned long long ull;

// ---------------- f32x2 packed-FMA helpers (2x FFMA throughput on sm_103a) ------
__device__ __forceinline__ ull pack2(float lo, float hi) {
    ull r;
    asm("mov.b64 %0, {%1,%2};" : "=l"(r) : "f"(lo), "f"(hi));
    return r;
}
__device__ __forceinline__ void unpack2(ull v, float& lo, float& hi) {
    asm("mov.b64 {%0,%1}, %2;" : "=f"(lo), "=f"(hi) : "l"(v));
}
__device__ __forceinline__ void dfma(ull& d, ull a, ull b) {
    asm("fma.rn.f32x2 %0, %1, %2, %0;" : "+l"(d) : "l"(a), "l"(b));
}

// ---------------- kernel 1: init g_agg[r] = x, zero stats ----------------------
__global__ void init_kernel(const float4* __restrict__ x4) {
    const int PER = NN * FF / 4;  // 1,600,000 float4
    int i = blockIdx.x * blockDim.x + threadIdx.x;
    int rel = blockIdx.y;
    if (i < PER) {
        ((float4*)g_agg)[(size_t)rel * PER + i] = x4[i];
    }
    if (rel == 0 && i < RR * FF) {
        g_sum[i] = 0.f;
        g_sumsq[i] = 0.f;
    }
}

// ---------------- kernel 2: edge scatter with vector atomics --------------------
__global__ void scatter_kernel(const int* __restrict__ ei,
                               const int* __restrict__ et,
                               const float4* __restrict__ x4) {
    int w = (blockIdx.x * blockDim.x + threadIdx.x) >> 5;  // one warp per edge
    int lane = threadIdx.x & 31;
    if (w >= EE) return;
    int dst = ei[w];        // edge_index[0][e]  (destination / segment row)
    int src = ei[EE + w];   // edge_index[1][e]  (source / gathered node)
    int r = et[w];
    float4 v = x4[(size_t)src * 32 + lane];
    float* p = g_agg + (((size_t)r * NN + dst) * FF + lane * 4);
    asm volatile("red.global.add.v4.f32 [%0], {%1,%2,%3,%4};"
                 :: "l"(p), "f"(v.x), "f"(v.y), "f"(v.z), "f"(v.w)
                 : "memory");
}

// ---------------- GEMM1: g_h[r] = g_agg[r] @ W1[r] + b1[r] ----------------------
// 128x128 tile, 256 threads, f32x2 inner loop. A tile XOR-swizzled in smem.
__global__ __launch_bounds__(256) void gemm1_kernel(const float* __restrict__ W1g,
                                                    const float* __restrict__ b1g) {
    extern __shared__ float sh[];
    float* As = sh;            // 128*128 floats, swizzled
    float* Ws = sh + 16384;    // 128*128 floats, row-major
    const int r = blockIdx.y;
    const int row0 = blockIdx.x * 128;
    const int tid = threadIdx.x;
    const int tx = tid & 15, ty = tid >> 4, ty8 = ty * 8;
    const int sw4 = (ty & 7) << 2;  // swizzle constant for compute-side A loads

    const float* A = g_agg + (size_t)r * (NN * FF);
    const float* W = W1g + r * (FF * FF);
    const float* bias = b1g + r * FF;

#pragma unroll
    for (int it = 0; it < 16; ++it) {
        int q = it * 256 + tid;
        ((float4*)Ws)[q] = ((const float4*)W)[q];
    }
#pragma unroll
    for (int it = 0; it < 16; ++it) {
        int q = it * 256 + tid;
        int row = q >> 5, c4 = q & 31;
        float4 v = make_float4(0.f, 0.f, 0.f, 0.f);
        int grow = row0 + row;
        if (grow < NN) v = ((const float4*)A)[(size_t)grow * 32 + c4];
        ((float4*)As)[row * 32 + (c4 ^ ((row >> 3) & 7))] = v;
    }
    __syncthreads();

    ull acc[8][4];
#pragma unroll
    for (int i = 0; i < 8; ++i)
#pragma unroll
        for (int jj = 0; jj < 4; ++jj)
            acc[i][jj] = pack2(bias[tx + 32 * jj], bias[tx + 32 * jj + 16]);

#pragma unroll 8
    for (int k = 0; k < FF; ++k) {
        ull b2[4];
#pragma unroll
        for (int jj = 0; jj < 4; ++jj)
            b2[jj] = pack2(Ws[k * FF + tx + 32 * jj], Ws[k * FF + tx + 32 * jj + 16]);
        int ks = k ^ sw4;
#pragma unroll
        for (int i = 0; i < 8; ++i) {
            float a = As[(ty8 + i) * FF + ks];
            ull a2 = pack2(a, a);
#pragma unroll
            for (int jj = 0; jj < 4; ++jj) dfma(acc[i][jj], a2, b2[jj]);
        }
    }

    float* H = g_h + (size_t)r * (NN * FF);
#pragma unroll
    for (int i = 0; i < 8; ++i) {
        int grow = row0 + ty8 + i;
        if (grow < NN) {
#pragma unroll
            for (int jj = 0; jj < 4; ++jj) {
                float lo, hi;
                unpack2(acc[i][jj], lo, hi);
                H[(size_t)grow * FF + tx + 32 * jj] = lo;
                H[(size_t)grow * FF + tx + 32 * jj + 16] = hi;
            }
        }
    }
}

// ---------------- BN stats: per-(r, channel) sum and sumsq over N ---------------
__global__ void stats_kernel() {
    const int CH = 512;
    int r = blockIdx.y;
    int row_begin = blockIdx.x * CH;
    int tid = threadIdx.x;
    int c = tid & 127, rr = tid >> 7;
    const float* H = g_h + (size_t)r * (NN * FF);
    float s = 0.f, s2 = 0.f;
    int row_end = row_begin + CH;
    if (row_end > NN) row_end = NN;
    for (int row = row_begin + rr; row < row_end; row += 2) {
        float v = H[(size_t)row * FF + c];
        s += v;
        s2 = fmaf(v, v, s2);
    }
    __shared__ float shs[256], shq[256];
    shs[tid] = s;
    shq[tid] = s2;
    __syncthreads();
    if (tid < 128) {
        atomicAdd(&g_sum[r * FF + c], shs[tid] + shs[tid + 128]);
        atomicAdd(&g_sumsq[r * FF + c], shq[tid] + shq[tid + 128]);
    }
}

// ---------------- finalize BN: scale/shift per (r, channel) ---------------------
__global__ void finalize_kernel(const float* __restrict__ gamma,
                                const float* __restrict__ beta) {
    int i = threadIdx.x + blockIdx.x * blockDim.x;
    if (i < RR * FF) {
        float inv_n = 1.0f / (float)NN;
        float mean = g_sum[i] * inv_n;
        float var = g_sumsq[i] * inv_n - mean * mean;
        if (var < 0.f) var = 0.f;
        float sc = gamma[i] * rsqrtf(var + 1e-5f);
        g_scale[i] = sc;
        g_shift[i] = beta[i] - mean * sc;
    }
}

// ---------------- GEMM2 fused: out = x@W_self + b_self + sum_r b2[r]
//                  + sum_r relu(bn(h_r)) @ W2[r] --------------------------------
__global__ __launch_bounds__(256) void gemm2_kernel(const float* __restrict__ x,
                                                    const float* __restrict__ Wself,
                                                    const float* __restrict__ bself,
                                                    const float* __restrict__ W2g,
                                                    const float* __restrict__ b2g,
                                                    float* __restrict__ out) {
    extern __shared__ float sh[];
    float* As = sh;
    float* Ws = sh + 16384;
    const int row0 = blockIdx.x * 128;
    const int tid = threadIdx.x;
    const int tx = tid & 15, ty = tid >> 4, ty8 = ty * 8;
    const int sw4 = (ty & 7) << 2;

    ull acc[8][4];
#pragma unroll
    for (int i = 0; i < 8; ++i)
#pragma unroll
        for (int jj = 0; jj < 4; ++jj) {
            int c0 = tx + 32 * jj, c1 = c0 + 16;
            float blo = bself[c0], bhi = bself[c1];
#pragma unroll
            for (int rr = 0; rr < RR; ++rr) {
                blo += b2g[rr * FF + c0];
                bhi += b2g[rr * FF + c1];
            }
            acc[i][jj] = pack2(blo, bhi);
        }

    for (int rel = 0; rel < 5; ++rel) {
        const float* A = (rel == 0) ? x : (g_h + (size_t)(rel - 1) * (NN * FF));
        const float* W = (rel == 0) ? Wself : (W2g + (rel - 1) * (FF * FF));
        const float* sc = g_scale + (rel - 1) * FF;
        const float* sf = g_shift + (rel - 1) * FF;

        __syncthreads();  // previous compute done reading smem
#pragma unroll
        for (int it = 0; it < 16; ++it) {
            int q = it * 256 + tid;
            ((float4*)Ws)[q] = ((const float4*)W)[q];
        }
#pragma unroll
        for (int it = 0; it < 16; ++it) {
            int q = it * 256 + tid;
            int row = q >> 5, c4 = q & 31;
            float4 v = make_float4(0.f, 0.f, 0.f, 0.f);
            int grow = row0 + row;
            if (grow < NN) v = ((const float4*)A)[(size_t)grow * 32 + c4];
            if (rel > 0) {
                int kb = c4 * 4;
                v.x = fmaxf(fmaf(v.x, sc[kb + 0], sf[kb + 0]), 0.f);
                v.y = fmaxf(fmaf(v.y, sc[kb + 1], sf[kb + 1]), 0.f);
                v.z = fmaxf(fmaf(v.z, sc[kb + 2], sf[kb + 2]), 0.f);
                v.w = fmaxf(fmaf(v.w, sc[kb + 3], sf[kb + 3]), 0.f);
            }
            ((float4*)As)[row * 32 + (c4 ^ ((row >> 3) & 7))] = v;
        }
        __syncthreads();

#pragma unroll 8
        for (int k = 0; k < FF; ++k) {
            ull b2[4];
#pragma unroll
            for (int jj = 0; jj < 4; ++jj)
                b2[jj] = pack2(Ws[k * FF + tx + 32 * jj], Ws[k * FF + tx + 32 * jj + 16]);
            int ks = k ^ sw4;
#pragma unroll
            for (int i = 0; i < 8; ++i) {
                float a = As[(ty8 + i) * FF + ks];
                ull a2 = pack2(a, a);
#pragma unroll
                for (int jj = 0; jj < 4; ++jj) dfma(acc[i][jj], a2, b2[jj]);
            }
        }
    }

#pragma unroll
    for (int i = 0; i < 8; ++i) {
        int grow = row0 + ty8 + i;
        if (grow < NN) {
#pragma unroll
            for (int jj = 0; jj < 4; ++jj) {
                float lo, hi;
                unpack2(acc[i][jj], lo, hi);
                out[(size_t)grow * FF + tx + 32 * jj] = lo;
                out[(size_t)grow * FF + tx + 32 * jj + 16] = hi;
            }
        }
    }
}

// ---------------- launch ---------------------------------------------------------
extern "C" void kernel_launch(void* const* d_in, const int* in_sizes, int n_in,
                              void* d_out, int out_size) {
    const float* x     = (const float*)d_in[0];
    const int*   ei    = (const int*)d_in[1];
    const int*   et    = (const int*)d_in[2];
    const float* Wself = (const float*)d_in[3];
    const float* bself = (const float*)d_in[4];
    const float* W1    = (const float*)d_in[5];
    const float* b1    = (const float*)d_in[6];
    const float* gamma = (const float*)d_in[7];
    const float* beta  = (const float*)d_in[8];
    const float* W2    = (const float*)d_in[9];
    const float* b2    = (const float*)d_in[10];
    float* out = (float*)d_out;

    const int SMEM = 2 * 16384 * 4;  // 128 KB dynamic shared
    cudaFuncSetAttribute(gemm1_kernel, cudaFuncAttributeMaxDynamicSharedMemorySize, SMEM);
    cudaFuncSetAttribute(gemm2_kernel, cudaFuncAttributeMaxDynamicSharedMemorySize, SMEM);

    const int PER4 = NN * FF / 4;
    init_kernel<<<dim3((PER4 + 255) / 256, RR), 256>>>((const float4*)x);
    scatter_kernel<<<(EE * 32) / 256, 256>>>(ei, et, (const float4*)x);
    gemm1_kernel<<<dim3((NN + 127) / 128, RR), 256, SMEM>>>(W1, b1);
    stats_kernel<<<dim3((NN + 511) / 512, RR), 256>>>();
    finalize_kernel<<<2, 256>>>(gamma, beta);
    gemm2_kernel<<<(NN + 127) / 128, 256, SMEM>>>(x, Wself, bself, W2, b2, out);
}

// round 2
// speedup vs baseline: 1.0194x; 1.0194x over previous
#include <cuda_runtime.h>

#define NN 50000
#define EE 600000
#define FF 128
#define RR 4
#define RN (RR * NN)          // 200000 segments
#define NBLK ((RN + 1023) / 1024)  // 196 scan blocks

// ---------------- scratch (static device globals; no allocation) ----------------
__device__ __align__(16) float g_agg[(size_t)RR * NN * FF];   // x + sum of neighbors
__device__ __align__(16) float g_h[(size_t)RR * NN * FF];     // output of first linear
__device__ float g_sum[RR * FF];
__device__ float g_sumsq[RR * FF];
__device__ float g_scale[RR * FF];
__device__ float g_shift[RR * FF];
__device__ int g_cnt[RN];     // per-segment edge count
__device__ int g_off[RN];     // intra-block exclusive scan of counts
__device__ int g_bsum[256];   // per-scan-block totals
__device__ int g_bscan[256];  // exclusive scan of block totals
__device__ int g_cur[RN];     // reorder cursors (zeroed)
__device__ int g_srcbuf[EE];  // edge sources sorted by segment

typedef unsigned long long ull;

// ---------------- f32x2 packed-FMA helpers (2x FFMA throughput on sm_103a) ------
__device__ __forceinline__ ull pack2(float lo, float hi) {
    ull r;
    asm("mov.b64 %0, {%1,%2};" : "=l"(r) : "f"(lo), "f"(hi));
    return r;
}
__device__ __forceinline__ void unpack2(ull v, float& lo, float& hi) {
    asm("mov.b64 {%0,%1}, %2;" : "=f"(lo), "=f"(hi) : "l"(v));
}
__device__ __forceinline__ void dfma(ull& d, ull a, ull b) {
    asm("fma.rn.f32x2 %0, %1, %2, %0;" : "+l"(d) : "l"(a), "l"(b));
}

// ---------------- histogram of segment ids (+ zero BN stats) --------------------
__global__ void hist_kernel(const int* __restrict__ ei, const int* __restrict__ et) {
    int e = blockIdx.x * blockDim.x + threadIdx.x;
    if (blockIdx.x == 0) {
        for (int i = threadIdx.x; i < RR * FF; i += blockDim.x) {
            g_sum[i] = 0.f;
            g_sumsq[i] = 0.f;
        }
    }
    if (e < EE) {
        int s = et[e] * NN + ei[e];
        atomicAdd(&g_cnt[s], 1);
    }
}

// ---------------- scan stage 1: per-1024-block exclusive scan -------------------
__global__ void scan1_kernel() {
    __shared__ int sh[512];
    int t = threadIdx.x;
    int base = blockIdx.x * 1024;
    int i0 = base + 2 * t, i1 = i0 + 1;
    int c0 = (i0 < RN) ? g_cnt[i0] : 0;
    int c1 = (i1 < RN) ? g_cnt[i1] : 0;
    int s = c0 + c1;
    sh[t] = s;
    __syncthreads();
    for (int d = 1; d < 512; d <<= 1) {
        int v = (t >= d) ? sh[t - d] : 0;
        __syncthreads();
        sh[t] += v;
        __syncthreads();
    }
    int excl = sh[t] - s;
    if (i0 < RN) g_off[i0] = excl;
    if (i1 < RN) g_off[i1] = excl + c0;
    if (t == 511) g_bsum[blockIdx.x] = sh[511];
}

// ---------------- scan stage 2: scan the 196 block totals -----------------------
__global__ void scan2_kernel() {
    __shared__ int sh[256];
    int t = threadIdx.x;
    int v = (t < NBLK) ? g_bsum[t] : 0;
    sh[t] = v;
    __syncthreads();
    for (int d = 1; d < 256; d <<= 1) {
        int u = (t >= d) ? sh[t - d] : 0;
        __syncthreads();
        sh[t] += u;
        __syncthreads();
    }
    g_bscan[t] = sh[t] - v;
}

// ---------------- reorder edges into segment-sorted order -----------------------
__global__ void reorder_kernel(const int* __restrict__ ei, const int* __restrict__ et) {
    int e = blockIdx.x * blockDim.x + threadIdx.x;
    if (e >= EE) return;
    int s = et[e] * NN + ei[e];
    int base = g_off[s] + g_bscan[s >> 10];
    int pos = base + atomicAdd(&g_cur[s], 1);
    g_srcbuf[pos] = ei[EE + e];
}

// ---------------- segmented sum: g_agg[seg] = x[row] + sum x[src] ----------------
__global__ void segsum_kernel(const float4* __restrict__ x4) {
    int warp = (blockIdx.x * blockDim.x + threadIdx.x) >> 5;
    int lane = threadIdx.x & 31;
    if (warp >= RN) return;
    int row = warp % NN;
    int start = g_off[warp] + g_bscan[warp >> 10];
    int cnt = g_cnt[warp];
    float4 acc = x4[(size_t)row * 32 + lane];
    for (int i = 0; i < cnt; ++i) {
        int src = g_srcbuf[start + i];
        float4 v = x4[(size_t)src * 32 + lane];
        acc.x += v.x; acc.y += v.y; acc.z += v.z; acc.w += v.w;
    }
    ((float4*)g_agg)[(size_t)warp * 32 + lane] = acc;
}

// ---------------- GEMM1: g_h[r] = g_agg[r] @ W1[r] + b1[r], fused BN stats -------
__global__ __launch_bounds__(256) void gemm1_kernel(const float* __restrict__ W1g,
                                                    const float* __restrict__ b1g) {
    extern __shared__ float sh[];
    float* As = sh;            // 128*128 floats, swizzled
    float* Ws = sh + 16384;    // 128*128 floats, row-major
    const int r = blockIdx.y;
    const int row0 = blockIdx.x * 128;
    const int tid = threadIdx.x;
    const int tx = tid & 15, ty = tid >> 4, ty8 = ty * 8;
    const int sw4 = (ty & 7) << 2;

    const float* A = g_agg + (size_t)r * (NN * FF);
    const float* W = W1g + r * (FF * FF);
    const float* bias = b1g + r * FF;

#pragma unroll
    for (int it = 0; it < 16; ++it) {
        int q = it * 256 + tid;
        ((float4*)Ws)[q] = ((const float4*)W)[q];
    }
#pragma unroll
    for (int it = 0; it < 16; ++it) {
        int q = it * 256 + tid;
        int row = q >> 5, c4 = q & 31;
        float4 v = make_float4(0.f, 0.f, 0.f, 0.f);
        int grow = row0 + row;
        if (grow < NN) v = ((const float4*)A)[(size_t)grow * 32 + c4];
        ((float4*)As)[row * 32 + (c4 ^ ((row >> 3) & 7))] = v;
    }
    __syncthreads();

    ull acc[8][4];
#pragma unroll
    for (int i = 0; i < 8; ++i)
#pragma unroll
        for (int jj = 0; jj < 4; ++jj)
            acc[i][jj] = pack2(bias[tx + 32 * jj], bias[tx + 32 * jj + 16]);

#pragma unroll 8
    for (int k = 0; k < FF; ++k) {
        ull b2[4];
#pragma unroll
        for (int jj = 0; jj < 4; ++jj)
            b2[jj] = pack2(Ws[k * FF + tx + 32 * jj], Ws[k * FF + tx + 32 * jj + 16]);
        int ks = k ^ sw4;
#pragma unroll
        for (int i = 0; i < 8; ++i) {
            float a = As[(ty8 + i) * FF + ks];
            ull a2 = pack2(a, a);
#pragma unroll
            for (int jj = 0; jj < 4; ++jj) dfma(acc[i][jj], a2, b2[jj]);
        }
    }

    float* H = g_h + (size_t)r * (NN * FF);
#pragma unroll
    for (int i = 0; i < 8; ++i) {
        int grow = row0 + ty8 + i;
        if (grow < NN) {
#pragma unroll
            for (int jj = 0; jj < 4; ++jj) {
                float lo, hi;
                unpack2(acc[i][jj], lo, hi);
                H[(size_t)grow * FF + tx + 32 * jj] = lo;
                H[(size_t)grow * FF + tx + 32 * jj + 16] = hi;
            }
        }
    }

    // ---- fused BN stats: column sums of this tile ----
    __syncthreads();              // done reading As/Ws; reuse smem
    sh[tid] = 0.f;                // [0,128) col sums, [128,256) col sumsq
    __syncthreads();
#pragma unroll
    for (int jj = 0; jj < 4; ++jj) {
        float slo = 0.f, qlo = 0.f, shi = 0.f, qhi = 0.f;
#pragma unroll
        for (int i = 0; i < 8; ++i) {
            if (row0 + ty8 + i < NN) {
                float lo, hi;
                unpack2(acc[i][jj], lo, hi);
                slo += lo; qlo = fmaf(lo, lo, qlo);
                shi += hi; qhi = fmaf(hi, hi, qhi);
            }
        }
        atomicAdd(&sh[tx + 32 * jj], slo);
        atomicAdd(&sh[128 + tx + 32 * jj], qlo);
        atomicAdd(&sh[tx + 32 * jj + 16], shi);
        atomicAdd(&sh[128 + tx + 32 * jj + 16], qhi);
    }
    __syncthreads();
    if (tid < 128) {
        atomicAdd(&g_sum[r * FF + tid], sh[tid]);
        atomicAdd(&g_sumsq[r * FF + tid], sh[128 + tid]);
    }
}

// ---------------- finalize BN: scale/shift per (r, channel) ---------------------
__global__ void finalize_kernel(const float* __restrict__ gamma,
                                const float* __restrict__ beta) {
    int i = threadIdx.x + blockIdx.x * blockDim.x;
    if (i < RR * FF) {
        float inv_n = 1.0f / (float)NN;
        float mean = g_sum[i] * inv_n;
        float var = g_sumsq[i] * inv_n - mean * mean;
        if (var < 0.f) var = 0.f;
        float sc = gamma[i] * rsqrtf(var + 1e-5f);
        g_scale[i] = sc;
        g_shift[i] = beta[i] - mean * sc;
    }
}

// ---------------- GEMM2 fused: out = x@W_self + b_self + sum_r b2[r]
//                  + sum_r relu(bn(h_r)) @ W2[r] --------------------------------
__global__ __launch_bounds__(256) void gemm2_kernel(const float* __restrict__ x,
                                                    const float* __restrict__ Wself,
                                                    const float* __restrict__ bself,
                                                    const float* __restrict__ W2g,
                                                    const float* __restrict__ b2g,
                                                    float* __restrict__ out) {
    extern __shared__ float sh[];
    float* As = sh;
    float* Ws = sh + 16384;
    const int row0 = blockIdx.x * 128;
    const int tid = threadIdx.x;
    const int tx = tid & 15, ty = tid >> 4, ty8 = ty * 8;
    const int sw4 = (ty & 7) << 2;

    ull acc[8][4];
#pragma unroll
    for (int i = 0; i < 8; ++i)
#pragma unroll
        for (int jj = 0; jj < 4; ++jj) {
            int c0 = tx + 32 * jj, c1 = c0 + 16;
            float blo = bself[c0], bhi = bself[c1];
#pragma unroll
            for (int rr = 0; rr < RR; ++rr) {
                blo += b2g[rr * FF + c0];
                bhi += b2g[rr * FF + c1];
            }
            acc[i][jj] = pack2(blo, bhi);
        }

    for (int rel = 0; rel < 5; ++rel) {
        const float* A = (rel == 0) ? x : (g_h + (size_t)(rel - 1) * (NN * FF));
        const float* W = (rel == 0) ? Wself : (W2g + (rel - 1) * (FF * FF));
        const float* sc = g_scale + (rel - 1) * FF;
        const float* sf = g_shift + (rel - 1) * FF;

        __syncthreads();
#pragma unroll
        for (int it = 0; it < 16; ++it) {
            int q = it * 256 + tid;
            ((float4*)Ws)[q] = ((const float4*)W)[q];
        }
#pragma unroll
        for (int it = 0; it < 16; ++it) {
            int q = it * 256 + tid;
            int row = q >> 5, c4 = q & 31;
            float4 v = make_float4(0.f, 0.f, 0.f, 0.f);
            int grow = row0 + row;
            if (grow < NN) v = ((const float4*)A)[(size_t)grow * 32 + c4];
            if (rel > 0) {
                int kb = c4 * 4;
                v.x = fmaxf(fmaf(v.x, sc[kb + 0], sf[kb + 0]), 0.f);
                v.y = fmaxf(fmaf(v.y, sc[kb + 1], sf[kb + 1]), 0.f);
                v.z = fmaxf(fmaf(v.z, sc[kb + 2], sf[kb + 2]), 0.f);
                v.w = fmaxf(fmaf(v.w, sc[kb + 3], sf[kb + 3]), 0.f);
            }
            ((float4*)As)[row * 32 + (c4 ^ ((row >> 3) & 7))] = v;
        }
        __syncthreads();

#pragma unroll 8
        for (int k = 0; k < FF; ++k) {
            ull b2[4];
#pragma unroll
            for (int jj = 0; jj < 4; ++jj)
                b2[jj] = pack2(Ws[k * FF + tx + 32 * jj], Ws[k * FF + tx + 32 * jj + 16]);
            int ks = k ^ sw4;
#pragma unroll
            for (int i = 0; i < 8; ++i) {
                float a = As[(ty8 + i) * FF + ks];
                ull a2 = pack2(a, a);
#pragma unroll
                for (int jj = 0; jj < 4; ++jj) dfma(acc[i][jj], a2, b2[jj]);
            }
        }
    }

#pragma unroll
    for (int i = 0; i < 8; ++i) {
        int grow = row0 + ty8 + i;
        if (grow < NN) {
#pragma unroll
            for (int jj = 0; jj < 4; ++jj) {
                float lo, hi;
                unpack2(acc[i][jj], lo, hi);
                out[(size_t)grow * FF + tx + 32 * jj] = lo;
                out[(size_t)grow * FF + tx + 32 * jj + 16] = hi;
            }
        }
    }
}

// ---------------- launch ---------------------------------------------------------
extern "C" void kernel_launch(void* const* d_in, const int* in_sizes, int n_in,
                              void* d_out, int out_size) {
    const float* x     = (const float*)d_in[0];
    const int*   ei    = (const int*)d_in[1];
    const int*   et    = (const int*)d_in[2];
    const float* Wself = (const float*)d_in[3];
    const float* bself = (const float*)d_in[4];
    const float* W1    = (const float*)d_in[5];
    const float* b1    = (const float*)d_in[6];
    const float* gamma = (const float*)d_in[7];
    const float* beta  = (const float*)d_in[8];
    const float* W2    = (const float*)d_in[9];
    const float* b2    = (const float*)d_in[10];
    float* out = (float*)d_out;

    void* p_cnt = nullptr;
    void* p_cur = nullptr;
    cudaGetSymbolAddress(&p_cnt, g_cnt);
    cudaGetSymbolAddress(&p_cur, g_cur);
    cudaMemsetAsync(p_cnt, 0, RN * sizeof(int));
    cudaMemsetAsync(p_cur, 0, RN * sizeof(int));

    const int SMEM = 2 * 16384 * 4;  // 128 KB dynamic shared
    cudaFuncSetAttribute(gemm1_kernel, cudaFuncAttributeMaxDynamicSharedMemorySize, SMEM);
    cudaFuncSetAttribute(gemm2_kernel, cudaFuncAttributeMaxDynamicSharedMemorySize, SMEM);

    hist_kernel<<<(EE + 255) / 256, 256>>>(ei, et);
    scan1_kernel<<<NBLK, 512>>>();
    scan2_kernel<<<1, 256>>>();
    reorder_kernel<<<(EE + 255) / 256, 256>>>(ei, et);
    segsum_kernel<<<(RN * 32 + 255) / 256, 256>>>((const float4*)x);
    gemm1_kernel<<<dim3((NN + 127) / 128, RR), 256, SMEM>>>(W1, b1);
    finalize_kernel<<<2, 256>>>(gamma, beta);
    gemm2_kernel<<<(NN + 127) / 128, 256, SMEM>>>(x, Wself, bself, W2, b2, out);
}